// round 4
// baseline (speedup 1.0000x reference)
#include <cuda_runtime.h>
#include <cstdint>

static constexpr int kNUsers = 100000;
static constexpr int kNItems = 500000;
static constexpr int kDim    = 64;
static constexpr int kNScore = 256;

static constexpr int ITILE  = 64;                                 // items per CTA tile
static constexpr int NTILES = (kNItems + ITILE - 1) / ITILE;      // 7813
static constexpr int PITCH  = 68;                                 // floats per row (64 + 4 pad)

// ---- SMEM layout (float offsets) ----
static constexpr int OF_USQ = 0;                       // 256 floats
static constexpr int OF_ISQ = 256;                     // 64 floats
static constexpr int OF_U   = 320;                     // 256 * 68 = 17408 floats
static constexpr int OF_I   = OF_U + 256 * PITCH;      // 17728
static constexpr int SMEM_FLOATS = OF_I + ITILE * PITCH;       // 22080
static constexpr unsigned SMEM_BYTES = SMEM_FLOATS * 4;        // 88320 B -> occupancy 2

__device__ __forceinline__ uint32_t f2tf32(float x) {
    uint32_t r;
    asm("cvt.rna.tf32.f32 %0, %1;" : "=r"(r) : "f"(x));
    return r;
}

__device__ __forceinline__ float rsum16(float sq) {
    // reduce across the 16 lanes that share one embedding row (c = lane & 15)
    sq += __shfl_xor_sync(0xffffffffu, sq, 1);
    sq += __shfl_xor_sync(0xffffffffu, sq, 2);
    sq += __shfl_xor_sync(0xffffffffu, sq, 4);
    sq += __shfl_xor_sync(0xffffffffu, sq, 8);
    return sq;
}

__global__ void __launch_bounds__(256, 2)
cml_kernel(const int* __restrict__ ids,
           const float* __restrict__ users,
           const float* __restrict__ items,
           float* __restrict__ out)
{
    extern __shared__ float smem[];
    float* usq = smem + OF_USQ;
    float* isq = smem + OF_ISQ;
    float* sU  = smem + OF_U;     // [256][PITCH] tf32 bits, user-major
    float* sI  = smem + OF_I;     // [64][PITCH]  tf32 bits, item-major

    const int tid  = threadIdx.x;
    const int lane = tid & 31;
    const int wid  = tid >> 5;
    const int c    = tid & 15;    // float4 chunk within a 64-dim row
    const int r0   = tid >> 4;    // base row (16 rows per sweep)

    // ---- stage all 256 users once: exact fp32 u_sq, rna-tf32 operand ----
    #pragma unroll
    for (int rr = 0; rr < 16; rr++) {
        const int r = r0 + rr * 16;
        const int uid = ids[r];
        float4 v = reinterpret_cast<const float4*>(users)[(size_t)uid * (kDim / 4) + c];
        float sq = rsum16(fmaf(v.x, v.x, fmaf(v.y, v.y, fmaf(v.z, v.z, v.w * v.w))));
        if (c == 0) usq[r] = sq;
        uint4 t4 = make_uint4(f2tf32(v.x), f2tf32(v.y), f2tf32(v.z), f2tf32(v.w));
        reinterpret_cast<uint4*>(sU + r * PITCH)[c] = t4;   // words r*68 + 4c: conflict-free
    }

    const int strip = (wid & 3) * 16;          // this warp's 16-item strip
    const int uhalf = (wid >> 2) * 128;        // this warp's 128-user half
    const int g = lane >> 2;                   // groupID
    const int t = lane & 3;                    // threadID_in_group

    for (int tile = blockIdx.x; tile < NTILES; tile += gridDim.x) {
        __syncthreads();   // prev iter's sI/isq reads done before overwrite

        const long ibase = (long)tile * ITILE;

        // ---- stage 64-item tile: exact fp32 i_sq, rna-tf32 operand ----
        #pragma unroll
        for (int rr = 0; rr < 4; rr++) {
            const int r = r0 + rr * 16;
            const long gi = ibase + r;
            float4 v = make_float4(0.f, 0.f, 0.f, 0.f);
            if (gi < kNItems)
                v = reinterpret_cast<const float4*>(items)[gi * (kDim / 4) + c];
            float sq = rsum16(fmaf(v.x, v.x, fmaf(v.y, v.y, fmaf(v.z, v.z, v.w * v.w))));
            if (c == 0) isq[r] = sq;
            uint4 t4 = make_uint4(f2tf32(v.x), f2tf32(v.y), f2tf32(v.z), f2tf32(v.w));
            reinterpret_cast<uint4*>(sI + r * PITCH)[c] = t4;
        }
        __syncthreads();

        // ---- 16 items x 128 users per warp via mma.sync m16n8k8 tf32 ----
        float acc[16][4];
        #pragma unroll
        for (int n = 0; n < 16; n++) {
            acc[n][0] = acc[n][1] = acc[n][2] = acc[n][3] = 0.f;
        }

        const uint32_t* aBase =
            reinterpret_cast<const uint32_t*>(sI + (strip + g) * PITCH + t);
        const uint32_t* bBase =
            reinterpret_cast<const uint32_t*>(sU + (uhalf + g) * PITCH + t);

        #pragma unroll 1
        for (int kb = 0; kb < kDim; kb += 8) {
            // A frag: a0=(g,t) a1=(g+8,t) a2=(g,t+4) a3=(g+8,t+4)
            const uint32_t a0 = aBase[kb];
            const uint32_t a1 = aBase[kb + 8 * PITCH];
            const uint32_t a2 = aBase[kb + 4];
            const uint32_t a3 = aBase[kb + 8 * PITCH + 4];
            #pragma unroll
            for (int n = 0; n < 16; n++) {
                // B frag (col-major): b0=(k=t, n=g) b1=(k=t+4, n=g)
                const uint32_t* bp = bBase + n * 8 * PITCH + kb;
                const uint32_t b0 = bp[0];
                const uint32_t b1 = bp[4];
                asm volatile(
                    "mma.sync.aligned.m16n8k8.row.col.f32.tf32.tf32.f32 "
                    "{%0,%1,%2,%3}, {%4,%5,%6,%7}, {%8,%9}, {%0,%1,%2,%3};"
                    : "+f"(acc[n][0]), "+f"(acc[n][1]),
                      "+f"(acc[n][2]), "+f"(acc[n][3])
                    : "r"(a0), "r"(a1), "r"(a2), "r"(a3), "r"(b0), "r"(b1));
            }
        }

        // ---- epilogue: score = 2*cross - usq - isq ----
        const float isq0 = isq[strip + g];
        const float isq1 = isq[strip + g + 8];
        const long  i0   = ibase + strip + g;
        const long  i1   = i0 + 8;
        const bool  v0   = i0 < kNItems;
        const bool  v1   = i1 < kNItems;

        #pragma unroll
        for (int n = 0; n < 16; n++) {
            const int u0 = uhalf + n * 8 + 2 * t;
            const float2 uq = *reinterpret_cast<const float2*>(usq + u0);
            float* p0 = out + (size_t)u0 * kNItems;
            float* p1 = p0 + (size_t)kNItems;
            if (v0) {
                p0[i0] = fmaf(2.f, acc[n][0], -(uq.x + isq0));
                p1[i0] = fmaf(2.f, acc[n][1], -(uq.y + isq0));
            }
            if (v1) {
                p0[i1] = fmaf(2.f, acc[n][2], -(uq.x + isq1));
                p1[i1] = fmaf(2.f, acc[n][3], -(uq.y + isq1));
            }
        }
    }
}

extern "C" void kernel_launch(void* const* d_in, const int* in_sizes, int n_in,
                              void* d_out, int out_size) {
    const int*   ids   = nullptr;
    const float* users = nullptr;
    const float* items = nullptr;
    for (int i = 0; i < n_in; i++) {
        if (in_sizes[i] == kNScore)              ids   = (const int*)d_in[i];
        else if (in_sizes[i] == kNUsers * kDim)  users = (const float*)d_in[i];
        else if (in_sizes[i] == kNItems * kDim)  items = (const float*)d_in[i];
    }
    cudaFuncSetAttribute(cml_kernel, cudaFuncAttributeMaxDynamicSharedMemorySize,
                         SMEM_BYTES);
    int sms = 0;
    if (cudaDeviceGetAttribute(&sms, cudaDevAttrMultiProcessorCount, 0) != cudaSuccess ||
        sms <= 0)
        sms = 148;
    cml_kernel<<<sms * 2, 256, SMEM_BYTES>>>(ids, users, items, (float*)d_out);
    (void)out_size;
}